// round 17
// baseline (speedup 1.0000x reference)
#include <cuda_runtime.h>
#include <cstdint>
#include <math.h>
#include <math_constants.h>

#define DIMS 32
#define NCAP 500000
#define TPB  512
#define MSLOTS 1024
#define PERMAX 3392           // >= ceil(500000/148)=3379
#define RES_PTS 768           // SMEM tier: 768*256B = 192KB per block
#define RSTR_PTS 1900         // L2 resident-target tier: 1900*256B*148 ~= 72MB (57% of L2)
#define DATA_BYTES ((size_t)RES_PTS * 16 * sizeof(float4))           // 196608
#define DYN_BYTES  (DATA_BYTES + (size_t)PERMAX * 2 * sizeof(float)) // 223744

// ---- static device scratch (no allocations allowed) ----
// 16 float4 columns: col k holds {x_k, s_k, x_{k+16}, s_{k+16}} for all points
__device__ float4 g_xs4[(size_t)16 * NCAP];
__device__ unsigned long long g_amin[MSLOTS];
__device__ unsigned g_cnt[MSLOTS];
__device__ volatile unsigned g_flag[MSLOTS];
__device__ unsigned long long g_res[MSLOTS];
__device__ float g_ell2v;

__device__ __forceinline__ unsigned f2ord(float f) {
    unsigned b = __float_as_uint(f);
    return (b & 0x80000000u) ? ~b : (b | 0x80000000u);
}

__global__ void k_setup(const unsigned* s0, const unsigned* s1) {
    int i = blockIdx.x * blockDim.x + threadIdx.x;
    if (i < MSLOTS) {
        g_amin[i] = 0xFFFFFFFFFFFFFFFFull;
        g_cnt[i] = 0u;
        g_flag[i] = 0u;
        g_res[i] = 0ull;
    }
    if (i == 0) {
        float ell = 1.0f;
        unsigned u0 = s0 ? s0[0] : 0u;
        unsigned u1 = s1 ? s1[0] : 0u;
        unsigned e0 = (u0 >> 23) & 0xffu;
        unsigned e1 = (u1 >> 23) & 0xffu;
        if (e0 >= 64u && e0 <= 191u)      ell = __uint_as_float(u0);
        else if (e1 >= 64u && e1 <= 191u) ell = __uint_as_float(u1);
        float e2 = __fmul_rn(ell, ell);
        if (!(e2 > 1e-20f) || !(e2 < 1e20f)) e2 = 1.0f;
        g_ell2v = e2;
    }
}

// x,s row-major [N][32] -> 16 float4 columns {x_k, s_k, x_{k+16}, s_{k+16}}
__global__ void __launch_bounds__(256) k_transpose(const float* __restrict__ x,
                                                   const float* __restrict__ sp,
                                                   int n) {
    int j = blockIdx.x * blockDim.x + threadIdx.x;
    if (j >= n) return;
    const float* xr = x  + (size_t)j * DIMS;
    const float* sr = sp + (size_t)j * DIMS;
    float xv[DIMS], sv[DIMS];
#pragma unroll
    for (int i = 0; i < DIMS / 4; i++) {
        float4 a = ((const float4*)xr)[i];
        float4 b = ((const float4*)sr)[i];
        xv[4*i] = a.x; xv[4*i+1] = a.y; xv[4*i+2] = a.z; xv[4*i+3] = a.w;
        sv[4*i] = b.x; sv[4*i+1] = b.y; sv[4*i+2] = b.z; sv[4*i+3] = b.w;
    }
#pragma unroll
    for (int k = 0; k < 16; k++)
        g_xs4[(size_t)k * n + j] = make_float4(xv[k], sv[k], xv[k + 16], sv[k + 16]);
}

__device__ __forceinline__ void argmin2(float& v, int& i, float v2, int i2) {
    if (v2 < v || (v2 == v && i2 < i)) { v = v2; i = i2; }
}

template <int NT>
__device__ __forceinline__ void block_argmin(float& v, int& i, float* rv, int* ri, int tid) {
#pragma unroll
    for (int off = 16; off > 0; off >>= 1) {
        float v2 = __shfl_down_sync(0xffffffffu, v, off);
        int   i2 = __shfl_down_sync(0xffffffffu, i, off);
        argmin2(v, i, v2, i2);
    }
    if ((tid & 31) == 0) { rv[tid >> 5] = v; ri[tid >> 5] = i; }
    __syncthreads();
    if (tid < 32) {
        const int nw = NT >> 5;
        float vv = (tid < nw) ? rv[tid] : CUDART_INF_F;
        int   ii = (tid < nw) ? ri[tid] : 0x7fffffff;
#pragma unroll
        for (int off = 16; off > 0; off >>= 1) {
            float v2 = __shfl_down_sync(0xffffffffu, vv, off);
            int   i2 = __shfl_down_sync(0xffffffffu, ii, off);
            argmin2(vv, ii, v2, i2);
        }
        if (tid == 0) { rv[0] = vv; ri[0] = ii; }
    }
    __syncthreads();
    v = rv[0]; i = ri[0];
}

// XLA tree over 32 (levels 2..4 applied to level-1-folded 8 partials)
__device__ __forceinline__ float tree8(float* q) {
#pragma unroll
    for (int k = 0; k < 4; k++) q[k] = __fadd_rn(q[k], q[k + 4]);
    q[0] = __fadd_rn(q[0], q[2]); q[1] = __fadd_rn(q[1], q[3]);
    return __fadd_rn(q[0], q[1]);
}
__device__ __forceinline__ float tree16(float* p) {
#pragma unroll
    for (int k = 0; k < 8; k++) p[k] = __fadd_rn(p[k], p[k + 8]);
    return tree8(p);
}

// Exchange: 1 atomicMin + 1 arrival atomic per block; last arriver publishes;
// others poll a plain volatile flag (parallel L2 reads, no atomic storm).
__device__ __forceinline__ int step_exchange(int t, float bv, int bi, int tid, int nb,
                                             unsigned long long* key_sh) {
    if (tid == 0) {
        unsigned long long key = ((unsigned long long)f2ord(bv) << 32) | (unsigned)bi;
        atomicMin(&g_amin[t], key);
        __threadfence();
        unsigned prev = atomicAdd(&g_cnt[t], 1u);
        if (prev == (unsigned)nb - 1u) {
            unsigned long long r = atomicAdd(&g_amin[t], 0ull);
            g_res[t] = r;
            __threadfence();
            g_flag[t] = 1u;
        } else {
            long spins = 0;
            while (g_flag[t] == 0u) {
                __nanosleep(64);
                if (++spins > 4000000L) break;
            }
        }
        __threadfence();
        *key_sh = atomicAdd(&g_res[t], 0ull);   // atomic read, coherent with writer
    }
    __syncthreads();
    return (int)(unsigned)(*key_sh & 0xffffffffull);
}

// ---- persistent kernel; 3-tier data: SMEM / L2-resident (plain) / streamed (ldcs) ----
__global__ void __launch_bounds__(TPB) k_stein_pers(
    const float* __restrict__ x, const float* __restrict__ logp,
    const float* __restrict__ sp, const float* __restrict__ lap,
    float* __restrict__ out, int nb, int n, int m, int per) {
    const int tid = threadIdx.x;
    const int bid = blockIdx.x;
    float ell2 = g_ell2v;
    if (!(ell2 > 1e-20f) || !(ell2 < 1e20f)) ell2 = 1.0f;
    const float e4 = __fmul_rn(ell2, ell2);
    const float w = __fdiv_rn(1.0f, (float)m);
    const float dterm = __fdiv_rn((float)DIMS, ell2);

    extern __shared__ char dyn_sh[];
    float4* dat_sh = (float4*)dyn_sh;                        // [16][rescnt]
    float*  obj_sh = (float*)(dyn_sh + DATA_BYTES);          // [PERMAX]
    float*  wlp_sh = obj_sh + PERMAX;                        // [PERMAX]

    __shared__ float piv[2 * DIMS];
    __shared__ float rv_sh[TPB / 32];
    __shared__ int   ri_sh[TPB / 32];
    __shared__ unsigned long long key_sh;

    const int j0  = bid * per;
    const int cnt = min(n - j0, per);
    const int rescnt = min(cnt, RES_PTS);
    const int rend   = min(cnt, RES_PTS + RSTR_PTS);   // end of L2-resident tier

    // Pin first rescnt points' data in SMEM (one-time copy; exact fp32 copies)
    for (int i = tid; i < rescnt * 16; i += TPB) {
        int k  = i / rescnt;
        int jl = i - k * rescnt;
        dat_sh[k * rescnt + jl] = g_xs4[(size_t)k * n + (j0 + jl)];
    }

    // ---- step 0 ----
    {
        float bv = CUDART_INF_F; int bi = 0x7fffffff;
        const float4* s4 = (const float4*)sp;
        for (int jl = tid; jl < cnt; jl += TPB) {
            int j = j0 + jl;
            float sv[DIMS];
            const float4* row = s4 + (size_t)j * (DIMS / 4);
#pragma unroll
            for (int i = 0; i < DIMS / 4; i++) {
                float4 v = row[i];
                sv[4*i] = v.x; sv[4*i+1] = v.y; sv[4*i+2] = v.z; sv[4*i+3] = v.w;
            }
            float p[16];
#pragma unroll
            for (int k = 0; k < 16; k++)
                p[k] = __fadd_rn(__fmul_rn(sv[k], sv[k]), __fmul_rn(sv[k+16], sv[k+16]));
            float s2 = tree16(p);
            float wl = __fmul_rn(w, logp[j]);
            wlp_sh[jl] = wl;
            float o = __fsub_rn(__fadd_rn(__fadd_rn(dterm, s2), lap[j]), wl);
            obj_sh[jl] = o;
            argmin2(bv, bi, o, j);
        }
        block_argmin<TPB>(bv, bi, rv_sh, ri_sh, tid);
        int idx = step_exchange(0, bv, bi, tid, nb, &key_sh);
        if (bid == 0 && tid == 0) out[0] = (float)idx;
        if (tid < 2 * DIMS)
            piv[tid] = (tid < DIMS) ? x[(size_t)idx * DIMS + tid]
                                    : sp[(size_t)idx * DIMS + (tid - DIMS)];
        __syncthreads();
    }

    // ---- steps 1..m-1, serpentine traversal (alternate direction per step) ----
    for (int t = 1; t < m; t++) {
        float bv = CUDART_INF_F; int bi = 0x7fffffff;
        const bool fwd = (t & 1);
        int jl = fwd ? tid : (cnt - 1 - tid);
        const int stepj = fwd ? TPB : -TPB;
        for (; fwd ? (jl < cnt) : (jl >= 0); jl += stepj) {
            int j = j0 + jl;
            const int tier = (jl < rescnt) ? 0 : ((jl < rend) ? 1 : 2);
            float qr[8], qa[8], qb[8], qc[8];
#pragma unroll
            for (int k = 0; k < 8; k++) {
                // col k -> dims (k, k+16); col k+8 -> dims (k+8, k+24)
                float4 A, B;
                if (tier == 0) {
                    A = dat_sh[k * rescnt + jl];
                    B = dat_sh[(k + 8) * rescnt + jl];
                } else if (tier == 1) {
                    A = g_xs4[(size_t)k * n + j];           // L2 resident-target
                    B = g_xs4[(size_t)(k + 8) * n + j];
                } else {
                    A = __ldcs(&g_xs4[(size_t)k * n + j]);  // evict-first stream
                    B = __ldcs(&g_xs4[(size_t)(k + 8) * n + j]);
                }
                float xk0 = piv[k],      sk0 = piv[DIMS + k];
                float xk1 = piv[k + 16], sk1 = piv[DIMS + k + 16];
                float xk2 = piv[k + 8],  sk2 = piv[DIMS + k + 8];
                float xk3 = piv[k + 24], sk3 = piv[DIMS + k + 24];
                float d0 = __fsub_rn(xk0, A.x);
                float d1 = __fsub_rn(xk1, A.z);
                float d2 = __fsub_rn(xk2, B.x);
                float d3 = __fsub_rn(xk3, B.z);
                float pr0 = __fadd_rn(__fmul_rn(d0, d0),   __fmul_rn(d1, d1));
                float pr1 = __fadd_rn(__fmul_rn(d2, d2),   __fmul_rn(d3, d3));
                qr[k] = __fadd_rn(pr0, pr1);
                float pa0 = __fadd_rn(__fmul_rn(d0, sk0),  __fmul_rn(d1, sk1));
                float pa1 = __fadd_rn(__fmul_rn(d2, sk2),  __fmul_rn(d3, sk3));
                qa[k] = __fadd_rn(pa0, pa1);
                float pb0 = __fadd_rn(__fmul_rn(A.y, d0),  __fmul_rn(A.w, d1));
                float pb1 = __fadd_rn(__fmul_rn(B.y, d2),  __fmul_rn(B.w, d3));
                qb[k] = __fadd_rn(pb0, pb1);
                float pc0 = __fadd_rn(__fmul_rn(A.y, sk0), __fmul_rn(A.w, sk1));
                float pc1 = __fadd_rn(__fmul_rn(B.y, sk2), __fmul_rn(B.w, sk3));
                qc[k] = __fadd_rn(pc0, pc1);
            }
            float r2   = tree8(qr);
            float a    = tree8(qa);
            float b    = tree8(qb);
            float sdot = tree8(qc);

            float q    = __fadd_rn(1.0f, __fdiv_rn(r2, ell2));
            float g    = powf(q, -1.5f);
            float p25  = powf(q, -2.5f);
            float rq   = rsqrtf(q);
            float cross = __fdiv_rn(__fsub_rn(a, b), ell2);
            float t1 = __fmul_rn(dterm, g);
            float t2 = __fmul_rn(__fdiv_rn(__fmul_rn(3.0f, r2), e4), p25);
            float t3 = __fmul_rn(cross, g);
            float t4 = __fmul_rn(sdot, rq);
            float ki = __fadd_rn(__fadd_rn(__fsub_rn(t1, t2), t3), t4);
            float o  = __fsub_rn(__fadd_rn(obj_sh[jl], __fmul_rn(2.0f, ki)), wlp_sh[jl]);
            obj_sh[jl] = o;
            argmin2(bv, bi, o, j);
        }
        block_argmin<TPB>(bv, bi, rv_sh, ri_sh, tid);
        int idx = step_exchange(t, bv, bi, tid, nb, &key_sh);
        if (bid == 0 && tid == 0) out[t] = (float)idx;
        __syncthreads();
        if (tid < 2 * DIMS)
            piv[tid] = (tid < DIMS) ? x[(size_t)idx * DIMS + tid]
                                    : sp[(size_t)idx * DIMS + (tid - DIMS)];
        __syncthreads();
    }
}

extern "C" void kernel_launch(void* const* d_in, const int* in_sizes, int n_in,
                              void* d_out, int out_size) {
    long maxsz = 0;
    for (int i = 0; i < n_in; i++) if ((long)in_sizes[i] > maxsz) maxsz = (long)in_sizes[i];
    long nsz = maxsz;
    for (int i = 0; i < n_in; i++) {
        long s = (long)in_sizes[i];
        if (s > 2 && s < nsz) nsz = s;
    }
    int N = (int)nsz;
    const float *x = nullptr, *sp = nullptr, *logp = nullptr, *lap = nullptr;
    const unsigned *s0 = nullptr, *s1 = nullptr;
    for (int i = 0; i < n_in; i++) {
        long s = (long)in_sizes[i];
        if (s == maxsz && s > 2) {
            if (!x) x = (const float*)d_in[i];
            else if (!sp) sp = (const float*)d_in[i];
        } else if (s == nsz && s > 2 && s != maxsz) {
            if (!logp) logp = (const float*)d_in[i];
            else if (!lap) lap = (const float*)d_in[i];
        } else if (s <= 2) {
            if (!s0) s0 = (const unsigned*)d_in[i];
            else if (!s1) s1 = (const unsigned*)d_in[i];
        }
    }
    if (!logp) { logp = x; lap = sp; }

    float* out = (float*)d_out;   // harness __output__ dtype: float32
    int m = out_size;
    if (m > MSLOTS) m = MSLOTS;

    int dev = 0;
    cudaGetDevice(&dev);
    int sms = 148;
    cudaDeviceGetAttribute(&sms, cudaDevAttrMultiProcessorCount, dev);
    int nb = sms;                       // 1 block/SM
    int per = (N + nb - 1) / nb;
    if (per > PERMAX) {
        per = PERMAX;
        nb = (N + per - 1) / per;
    }

    cudaFuncSetAttribute(k_stein_pers, cudaFuncAttributeMaxDynamicSharedMemorySize,
                         (int)DYN_BYTES);

    k_setup<<<(MSLOTS + 255) / 256, 256>>>(s0, s1);
    k_transpose<<<(N + 255) / 256, 256>>>(x, sp, N);
    k_stein_pers<<<nb, TPB, DYN_BYTES>>>(x, logp, sp, lap, out, nb, N, m, per);
}